// round 1
// baseline (speedup 1.0000x reference)
#include <cuda_runtime.h>
#include <cuda_bf16.h>

// Causal BoW == running mean along T: out[b,t,c] = (sum_{i<=t} x[b,i,c]) / (t+1)
// Shapes fixed by the reference: B=32, T=2048, C=512, fp32.
//
// Strategy: one thread per (b,c) column (16384 threads, single wave of
// 128 CTAs x 128 threads). Each thread walks T serially keeping the running
// sum in a register. Adjacent threads hold adjacent c -> every LDG/STG is a
// fully coalesced 128B line per warp. Latency is hidden by batching 32
// independent loads per iteration (MLP=32 per warp), since occupancy is
// intentionally tiny. 1/(t+1) lives in shared memory (broadcast LDS, no
// LDG-queue pressure, no per-element RCP).

#define B_DIM 32
#define T_DIM 2048
#define C_DIM 512
#define UNROLL 32
#define BLOCK 128

__global__ __launch_bounds__(BLOCK, 1)
void causal_bow_kernel(const float* __restrict__ x, float* __restrict__ out) {
    __shared__ float s_inv[T_DIM];
    for (int i = threadIdx.x; i < T_DIM; i += BLOCK) {
        s_inv[i] = 1.0f / (float)(i + 1);
    }
    __syncthreads();

    int col = blockIdx.x * BLOCK + threadIdx.x;      // 0 .. B*C-1
    int b = col >> 9;                                 // col / 512
    int c = col & (C_DIM - 1);                        // col % 512

    const float* __restrict__ xp = x + (size_t)b * T_DIM * C_DIM + c;
    float* __restrict__ op = out + (size_t)b * T_DIM * C_DIM + c;

    float s = 0.0f;

    #pragma unroll 1
    for (int t0 = 0; t0 < T_DIM; t0 += UNROLL) {
        float v[UNROLL];
        // Batch of independent loads -> 32 outstanding 128B lines per warp.
        #pragma unroll
        for (int u = 0; u < UNROLL; ++u) {
            v[u] = __ldg(xp + (size_t)(t0 + u) * C_DIM);
        }
        // Serial accumulate + scaled store (stores are fire-and-forget).
        #pragma unroll
        for (int u = 0; u < UNROLL; ++u) {
            s += v[u];
            op[(size_t)(t0 + u) * C_DIM] = s * s_inv[t0 + u];
        }
    }
}

extern "C" void kernel_launch(void* const* d_in, const int* in_sizes, int n_in,
                              void* d_out, int out_size) {
    const float* x = (const float*)d_in[0];
    float* out = (float*)d_out;
    (void)in_sizes; (void)n_in; (void)out_size;

    dim3 grid((B_DIM * C_DIM) / BLOCK);   // 128 CTAs, single wave
    dim3 block(BLOCK);
    causal_bow_kernel<<<grid, block>>>(x, out);
}

// round 3
// speedup vs baseline: 1.1807x; 1.1807x over previous
#include <cuda_runtime.h>
#include <cuda_bf16.h>

// Causal BoW = running mean along T. Shapes: B=32, T=2048, C=512, fp32.
//
// Single-pass decoupled-lookback scan (CUB-style, fence-based):
//  tile = (chain, tk): chain = (b, c-half) -> 64 chains; tk = chunk of
//  R=32 rows -> 64 chunks/chain; 4096 tiles total.
//  256-thread CTA = one thread per column, 32 rows in registers.
//  Publish protocol per tile: store 256 floats (st.cg) -> __threadfence()
//  -> set flag (1=aggregate ready, 2=inclusive ready). Lookback: thread 0
//  spins on predecessor flag (volatile), smem-broadcast, __threadfence(),
//  then all threads read values with __ldcg. Atomic ticket gives tiles
//  scheduling order -> deadlock-free. Clear kernel resets 4096 flags +
//  ticket each replay (graph-safe; __device__ globals only, no allocs).

#define B_DIM 32
#define T_DIM 2048
#define C_DIM 512
#define R_ROWS 32
#define CGROUP 256
#define NCHAINS (B_DIM * (C_DIM / CGROUP))   // 64
#define NTK (T_DIM / R_ROWS)                 // 64
#define NTILES (NCHAINS * NTK)               // 4096

__device__ float g_aggr[(size_t)NTILES * CGROUP];   // 4 MB: tile local sums
__device__ float g_incl[(size_t)NTILES * CGROUP];   // 4 MB: tile inclusive prefixes
__device__ int   g_flag[NTILES];                     // 0=none 1=aggr 2=incl
__device__ unsigned int g_ticket;

__global__ void clear_kernel() {
    int i = blockIdx.x * blockDim.x + threadIdx.x;   // 16*256 = 4096 threads
    g_flag[i] = 0;
    if (i == 0) g_ticket = 0u;
}

__global__ __launch_bounds__(CGROUP)
void causal_bow_scan(const float* __restrict__ x, float* __restrict__ out) {
    __shared__ unsigned s_tile;
    __shared__ int s_stat;
    __shared__ float s_inv[R_ROWS];

    const int tid = threadIdx.x;
    if (tid == 0) s_tile = atomicAdd(&g_ticket, 1u);
    __syncthreads();

    const unsigned vt = s_tile;
    const unsigned chain = vt % NCHAINS;
    const unsigned tk = vt / NCHAINS;
    const unsigned b  = chain >> 1;
    const unsigned ch = chain & 1;
    const unsigned c  = ch * CGROUP + tid;
    const int t0 = tk * R_ROWS;

    if (tid < R_ROWS)
        s_inv[tid] = 1.0f / (float)(t0 + tid + 1);

    const size_t base = (size_t)b * T_DIM * C_DIM + (size_t)t0 * C_DIM + c;
    const float* __restrict__ xp = x + base;
    float* __restrict__ op = out + base;

    // Batched independent loads: 32 coalesced 128B lines in flight per warp.
    float v[R_ROWS];
    #pragma unroll
    for (int u = 0; u < R_ROWS; ++u)
        v[u] = __ldg(xp + (size_t)u * C_DIM);

    // Local inclusive scan in registers.
    #pragma unroll
    for (int u = 1; u < R_ROWS; ++u)
        v[u] += v[u - 1];
    const float total = v[R_ROWS - 1];

    const size_t slot = (size_t)vt * CGROUP + tid;
    float prefix = 0.0f;

    if (tk == 0) {
        __stcg(&g_incl[slot], total);
        __threadfence();
        __syncthreads();
        if (tid == 0) atomicExch(&g_flag[vt], 2);
    } else {
        // Publish aggregate so successors can make progress immediately.
        __stcg(&g_aggr[slot], total);
        __threadfence();
        __syncthreads();
        if (tid == 0) atomicExch(&g_flag[vt], 1);

        // Lookback over predecessors in the same chain.
        for (int j = (int)vt - NCHAINS; j >= 0; j -= NCHAINS) {
            if (tid == 0) {
                volatile int* fp = &g_flag[j];
                int f;
                do { f = *fp; } while (f == 0);
                s_stat = f;
            }
            __syncthreads();
            const int f = s_stat;
            __threadfence();   // acquire: order value loads after flag read
            const float* src = (f == 2 ? g_incl : g_aggr) + (size_t)j * CGROUP;
            prefix += __ldcg(src + tid);
            if (f == 2) break;
            __syncthreads();   // protect s_stat before next iteration
        }

        __stcg(&g_incl[slot], prefix + total);
        __threadfence();
        __syncthreads();
        if (tid == 0) atomicExch(&g_flag[vt], 2);
    }

    // Scaled output: (prefix + local inclusive) / (t+1).
    #pragma unroll
    for (int u = 0; u < R_ROWS; ++u)
        op[(size_t)u * C_DIM] = (prefix + v[u]) * s_inv[u];
}

extern "C" void kernel_launch(void* const* d_in, const int* in_sizes, int n_in,
                              void* d_out, int out_size) {
    const float* x = (const float*)d_in[0];
    float* out = (float*)d_out;
    (void)in_sizes; (void)n_in; (void)out_size;

    clear_kernel<<<NTILES / 256, 256>>>();
    causal_bow_scan<<<NTILES, CGROUP>>>(x, out);
}